// round 3
// baseline (speedup 1.0000x reference)
#include <cuda_runtime.h>
#include <math.h>
#include <stdint.h>

// Problem dims (fixed by the dataset)
#define Bd 2
#define Td 2048
#define Cd 1024
#define Hd 16
#define Dd 64

// Scratch: qkv [B,T,3C] and attention output [B,T,C]
__device__ float g_qkv[(size_t)Bd * Td * 3 * Cd];
__device__ float g_att[(size_t)Bd * Td * Cd];

// ---------------------------------------------------------------------------
// TF32 tensor-core GEMM + bias: C[M,N] = A[M,K] @ B[K,N] + bias[N]
// 128x128 block tile, BK=32, 8 warps (2x4), 64x32 warp tile, m16n8k8 mma.
// ---------------------------------------------------------------------------
#define GBM 128
#define GBN 128
#define GBK 32

__device__ __forceinline__ uint32_t f2tf32(float x) {
    uint32_t r;
    asm("cvt.rna.tf32.f32 %0, %1;" : "=r"(r) : "f"(x));
    return r;
}

__global__ __launch_bounds__(256) void gemm_tf32_bias(
    const float* __restrict__ A, const float* __restrict__ B,
    const float* __restrict__ bias, float* __restrict__ C,
    int M, int N, int K)
{
    // As: [row][k], stride 36 -> conflict-free frag loads (bank = 4*row + k)
    // Bs: [k][n],  stride 136 -> conflict-free frag loads (bank = 8*k + n)
    __shared__ __align__(16) float As[GBM][GBK + 4];
    __shared__ __align__(16) float Bs[GBK][GBN + 8];

    const int tid  = threadIdx.x;
    const int warp = tid >> 5;
    const int lane = tid & 31;
    const int wm = warp >> 2;          // 0..1
    const int wn = warp & 3;           // 0..3
    const int g  = lane >> 2;          // 0..7
    const int cc = lane & 3;           // 0..3

    const int row0 = blockIdx.y * GBM;
    const int col0 = blockIdx.x * GBN;

    float acc[4][4][4];
    #pragma unroll
    for (int mt = 0; mt < 4; mt++)
        #pragma unroll
        for (int nt = 0; nt < 4; nt++)
            #pragma unroll
            for (int q = 0; q < 4; q++) acc[mt][nt][q] = 0.0f;

    for (int k0 = 0; k0 < K; k0 += GBK) {
        // A tile: 128 rows x 32 k -> 1024 float4, 4 per thread
        #pragma unroll
        for (int i = 0; i < 4; i++) {
            int idx = tid + i * 256;
            int r   = idx >> 3;        // 0..127
            int c4  = idx & 7;         // 0..7
            float4 v = *reinterpret_cast<const float4*>(
                A + (size_t)(row0 + r) * K + k0 + c4 * 4);
            float4 w;
            w.x = __uint_as_float(f2tf32(v.x));
            w.y = __uint_as_float(f2tf32(v.y));
            w.z = __uint_as_float(f2tf32(v.z));
            w.w = __uint_as_float(f2tf32(v.w));
            *reinterpret_cast<float4*>(&As[r][c4 * 4]) = w;
        }
        // B tile: 32 k x 128 n -> 1024 float4, 4 per thread
        #pragma unroll
        for (int i = 0; i < 4; i++) {
            int idx = tid + i * 256;
            int r   = idx >> 5;        // k row 0..31
            int c4  = idx & 31;        // 0..31
            float4 v = *reinterpret_cast<const float4*>(
                B + (size_t)(k0 + r) * N + col0 + c4 * 4);
            float4 w;
            w.x = __uint_as_float(f2tf32(v.x));
            w.y = __uint_as_float(f2tf32(v.y));
            w.z = __uint_as_float(f2tf32(v.z));
            w.w = __uint_as_float(f2tf32(v.w));
            *reinterpret_cast<float4*>(&Bs[r][c4 * 4]) = w;
        }
        __syncthreads();

        #pragma unroll
        for (int kk = 0; kk < GBK / 8; kk++) {
            const int kc = kk * 8 + cc;
            // A fragments: 4 m-tiles
            uint32_t a[4][4];
            #pragma unroll
            for (int mt = 0; mt < 4; mt++) {
                int r = wm * 64 + mt * 16 + g;
                a[mt][0] = __float_as_uint(As[r][kc]);
                a[mt][1] = __float_as_uint(As[r + 8][kc]);
                a[mt][2] = __float_as_uint(As[r][kc + 4]);
                a[mt][3] = __float_as_uint(As[r + 8][kc + 4]);
            }
            // B fragments: 4 n-tiles
            uint32_t b[4][2];
            #pragma unroll
            for (int nt = 0; nt < 4; nt++) {
                int n = wn * 32 + nt * 8 + g;
                b[nt][0] = __float_as_uint(Bs[kc][n]);
                b[nt][1] = __float_as_uint(Bs[kc + 4][n]);
            }
            #pragma unroll
            for (int mt = 0; mt < 4; mt++)
                #pragma unroll
                for (int nt = 0; nt < 4; nt++) {
                    asm volatile(
                        "mma.sync.aligned.m16n8k8.row.col.f32.tf32.tf32.f32 "
                        "{%0,%1,%2,%3}, {%4,%5,%6,%7}, {%8,%9}, {%0,%1,%2,%3};"
                        : "+f"(acc[mt][nt][0]), "+f"(acc[mt][nt][1]),
                          "+f"(acc[mt][nt][2]), "+f"(acc[mt][nt][3])
                        : "r"(a[mt][0]), "r"(a[mt][1]), "r"(a[mt][2]), "r"(a[mt][3]),
                          "r"(b[nt][0]), "r"(b[nt][1]));
                }
        }
        __syncthreads();
    }

    // Epilogue: bias + store (float2 per fragment half)
    #pragma unroll
    for (int mt = 0; mt < 4; mt++) {
        int r = row0 + wm * 64 + mt * 16 + g;
        #pragma unroll
        for (int nt = 0; nt < 4; nt++) {
            int n = col0 + wn * 32 + nt * 8 + cc * 2;
            float2 bb = *reinterpret_cast<const float2*>(bias + n);
            float2 o0, o1;
            o0.x = acc[mt][nt][0] + bb.x;
            o0.y = acc[mt][nt][1] + bb.y;
            o1.x = acc[mt][nt][2] + bb.x;
            o1.y = acc[mt][nt][3] + bb.y;
            *reinterpret_cast<float2*>(C + (size_t)r * N + n)       = o0;
            *reinterpret_cast<float2*>(C + (size_t)(r + 8) * N + n) = o1;
        }
    }
}

// ---------------------------------------------------------------------------
// Causal flash attention, deferred-rescale (16-key chunks).
// Grid: (T/BQ, B*H). 128 threads, one query row per thread.
// ---------------------------------------------------------------------------
#define BQ  128
#define BKV 64
#define CHK 16

__global__ __launch_bounds__(128) void attn_kernel()
{
    const int qt  = blockIdx.x;
    const int bh  = blockIdx.y;
    const int b   = bh / Hd;
    const int h   = bh % Hd;
    const int tid = threadIdx.x;
    const int t   = qt * BQ + tid;

    __shared__ __align__(16) float Ks[BKV][Dd];
    __shared__ __align__(16) float Vs[BKV][Dd];

    const float* qkv_b = g_qkv + (size_t)b * Td * 3 * Cd;
    const int koff = Cd + h * Dd;
    const int voff = 2 * Cd + h * Dd;

    float q[Dd];
    {
        const float* qrow = qkv_b + (size_t)t * 3 * Cd + h * Dd;
        const float scale = 0.125f;   // 1/sqrt(64)
        #pragma unroll
        for (int d4 = 0; d4 < Dd / 4; d4++) {
            float4 v = *reinterpret_cast<const float4*>(qrow + d4 * 4);
            q[d4 * 4 + 0] = v.x * scale;
            q[d4 * 4 + 1] = v.y * scale;
            q[d4 * 4 + 2] = v.z * scale;
            q[d4 * 4 + 3] = v.w * scale;
        }
    }

    float m = -INFINITY, l = 0.0f;
    float o[Dd];
    #pragma unroll
    for (int d = 0; d < Dd; d++) o[d] = 0.0f;

    const int nkt = (qt * BQ + BQ + BKV - 1) / BKV;

    for (int kt = 0; kt < nkt; kt++) {
        __syncthreads();
        #pragma unroll
        for (int i = 0; i < 8; i++) {
            int idx = tid + i * 128;
            int r   = idx >> 4;
            int c4  = idx & 15;
            const float* src = qkv_b + (size_t)(kt * BKV + r) * 3 * Cd;
            *reinterpret_cast<float4*>(&Ks[r][c4 * 4]) =
                *reinterpret_cast<const float4*>(src + koff + c4 * 4);
            *reinterpret_cast<float4*>(&Vs[r][c4 * 4]) =
                *reinterpret_cast<const float4*>(src + voff + c4 * 4);
        }
        __syncthreads();

        int jmax = t - kt * BKV + 1;
        if (jmax > BKV) jmax = BKV;

        for (int jb = 0; jb < jmax; jb += CHK) {
            const int cnt = min(CHK, jmax - jb);

            // scores for this chunk
            float s[CHK];
            float cmax = -INFINITY;
            #pragma unroll
            for (int jj = 0; jj < CHK; jj++) {
                if (jj < cnt) {
                    const int j = jb + jj;
                    float s0 = 0.f, s1 = 0.f, s2 = 0.f, s3 = 0.f;
                    #pragma unroll
                    for (int d = 0; d < Dd; d += 4) {
                        float4 kv = *reinterpret_cast<const float4*>(&Ks[j][d]);
                        s0 = fmaf(q[d + 0], kv.x, s0);
                        s1 = fmaf(q[d + 1], kv.y, s1);
                        s2 = fmaf(q[d + 2], kv.z, s2);
                        s3 = fmaf(q[d + 3], kv.w, s3);
                    }
                    s[jj] = (s0 + s1) + (s2 + s3);
                    cmax = fmaxf(cmax, s[jj]);
                }
            }

            // one rescale per chunk
            const float mn = fmaxf(m, cmax);
            const float sc = __expf(m - mn);
            m = mn;
            l *= sc;
            #pragma unroll
            for (int d = 0; d < Dd; d++) o[d] *= sc;

            // accumulate
            #pragma unroll
            for (int jj = 0; jj < CHK; jj++) {
                if (jj < cnt) {
                    const int j = jb + jj;
                    const float p = __expf(s[jj] - mn);
                    l += p;
                    #pragma unroll
                    for (int d = 0; d < Dd; d += 4) {
                        float4 vv = *reinterpret_cast<const float4*>(&Vs[j][d]);
                        o[d + 0] = fmaf(p, vv.x, o[d + 0]);
                        o[d + 1] = fmaf(p, vv.y, o[d + 1]);
                        o[d + 2] = fmaf(p, vv.z, o[d + 2]);
                        o[d + 3] = fmaf(p, vv.w, o[d + 3]);
                    }
                }
            }
        }
    }

    const float inv = 1.0f / l;
    float* dst = g_att + ((size_t)b * Td + t) * Cd + h * Dd;
    #pragma unroll
    for (int d = 0; d < Dd; d += 4) {
        float4 ov;
        ov.x = o[d + 0] * inv;
        ov.y = o[d + 1] * inv;
        ov.z = o[d + 2] * inv;
        ov.w = o[d + 3] * inv;
        *reinterpret_cast<float4*>(dst + d) = ov;
    }
}

// ---------------------------------------------------------------------------
// Launch
// ---------------------------------------------------------------------------
extern "C" void kernel_launch(void* const* d_in, const int* in_sizes, int n_in,
                              void* d_out, int out_size)
{
    const float* x      = (const float*)d_in[0];
    // d_in[1] = attn_mask: tril by construction; causality handled structurally
    const float* W_attn = (const float*)d_in[2];
    const float* b_attn = (const float*)d_in[3];
    const float* W_proj = (const float*)d_in[4];
    const float* b_proj = (const float*)d_in[5];
    float* out = (float*)d_out;

    float* qkv = nullptr;
    float* att = nullptr;
    cudaGetSymbolAddress((void**)&qkv, g_qkv);
    cudaGetSymbolAddress((void**)&att, g_att);

    const int M = Bd * Td;     // 4096

    // 1) QKV = x @ W_attn + b_attn : [4096,1024] x [1024,3072]
    {
        dim3 grid((3 * Cd) / GBN, M / GBM);
        gemm_tf32_bias<<<grid, 256>>>(x, W_attn, b_attn, qkv, M, 3 * Cd, Cd);
    }
    // 2) causal attention per (b,h)
    {
        dim3 grid(Td / BQ, Bd * Hd);
        attn_kernel<<<grid, 128>>>();
    }
    // 3) out = att @ W_proj + b_proj : [4096,1024] x [1024,1024]
    {
        dim3 grid(Cd / GBN, M / GBM);
        gemm_tf32_bias<<<grid, 256>>>(att, W_proj, b_proj, out, M, Cd, Cd);
    }
}

// round 4
// speedup vs baseline: 2.1257x; 2.1257x over previous
#include <cuda_runtime.h>
#include <math.h>
#include <stdint.h>

// Problem dims (fixed by the dataset)
#define Bd 2
#define Td 2048
#define Cd 1024
#define Hd 16
#define Dd 64

// Scratch: qkv [B,T,3C] and attention output [B,T,C]
__device__ float g_qkv[(size_t)Bd * Td * 3 * Cd];
__device__ float g_att[(size_t)Bd * Td * Cd];

__device__ __forceinline__ uint32_t f2tf32(float x) {
    uint32_t r;
    asm("cvt.rna.tf32.f32 %0, %1;" : "=r"(r) : "f"(x));
    return r;
}

__device__ __forceinline__ void mma_tf32(float* c, const uint32_t* a,
                                         uint32_t b0, uint32_t b1) {
    asm volatile(
        "mma.sync.aligned.m16n8k8.row.col.f32.tf32.tf32.f32 "
        "{%0,%1,%2,%3}, {%4,%5,%6,%7}, {%8,%9}, {%0,%1,%2,%3};"
        : "+f"(c[0]), "+f"(c[1]), "+f"(c[2]), "+f"(c[3])
        : "r"(a[0]), "r"(a[1]), "r"(a[2]), "r"(a[3]), "r"(b0), "r"(b1));
}

// ---------------------------------------------------------------------------
// TF32 tensor-core GEMM + bias: C[M,N] = A[M,K] @ B[K,N] + bias[N]
// 128x128 block tile, BK=32, 8 warps (2x4), 64x32 warp tile, m16n8k8 mma.
// ---------------------------------------------------------------------------
#define GBM 128
#define GBN 128
#define GBK 32

__global__ __launch_bounds__(256) void gemm_tf32_bias(
    const float* __restrict__ A, const float* __restrict__ B,
    const float* __restrict__ bias, float* __restrict__ C,
    int M, int N, int K)
{
    __shared__ __align__(16) float As[GBM][GBK + 4];
    __shared__ __align__(16) float Bs[GBK][GBN + 8];

    const int tid  = threadIdx.x;
    const int warp = tid >> 5;
    const int lane = tid & 31;
    const int wm = warp >> 2;
    const int wn = warp & 3;
    const int g  = lane >> 2;
    const int cc = lane & 3;

    const int row0 = blockIdx.y * GBM;
    const int col0 = blockIdx.x * GBN;

    float acc[4][4][4];
    #pragma unroll
    for (int mt = 0; mt < 4; mt++)
        #pragma unroll
        for (int nt = 0; nt < 4; nt++)
            #pragma unroll
            for (int q = 0; q < 4; q++) acc[mt][nt][q] = 0.0f;

    for (int k0 = 0; k0 < K; k0 += GBK) {
        #pragma unroll
        for (int i = 0; i < 4; i++) {
            int idx = tid + i * 256;
            int r   = idx >> 3;
            int c4  = idx & 7;
            float4 v = *reinterpret_cast<const float4*>(
                A + (size_t)(row0 + r) * K + k0 + c4 * 4);
            float4 w;
            w.x = __uint_as_float(f2tf32(v.x));
            w.y = __uint_as_float(f2tf32(v.y));
            w.z = __uint_as_float(f2tf32(v.z));
            w.w = __uint_as_float(f2tf32(v.w));
            *reinterpret_cast<float4*>(&As[r][c4 * 4]) = w;
        }
        #pragma unroll
        for (int i = 0; i < 4; i++) {
            int idx = tid + i * 256;
            int r   = idx >> 5;
            int c4  = idx & 31;
            float4 v = *reinterpret_cast<const float4*>(
                B + (size_t)(k0 + r) * N + col0 + c4 * 4);
            float4 w;
            w.x = __uint_as_float(f2tf32(v.x));
            w.y = __uint_as_float(f2tf32(v.y));
            w.z = __uint_as_float(f2tf32(v.z));
            w.w = __uint_as_float(f2tf32(v.w));
            *reinterpret_cast<float4*>(&Bs[r][c4 * 4]) = w;
        }
        __syncthreads();

        #pragma unroll
        for (int kk = 0; kk < GBK / 8; kk++) {
            const int kc = kk * 8 + cc;
            uint32_t a[4][4];
            #pragma unroll
            for (int mt = 0; mt < 4; mt++) {
                int r = wm * 64 + mt * 16 + g;
                a[mt][0] = __float_as_uint(As[r][kc]);
                a[mt][1] = __float_as_uint(As[r + 8][kc]);
                a[mt][2] = __float_as_uint(As[r][kc + 4]);
                a[mt][3] = __float_as_uint(As[r + 8][kc + 4]);
            }
            uint32_t b[4][2];
            #pragma unroll
            for (int nt = 0; nt < 4; nt++) {
                int n = wn * 32 + nt * 8 + g;
                b[nt][0] = __float_as_uint(Bs[kc][n]);
                b[nt][1] = __float_as_uint(Bs[kc + 4][n]);
            }
            #pragma unroll
            for (int mt = 0; mt < 4; mt++)
                #pragma unroll
                for (int nt = 0; nt < 4; nt++)
                    mma_tf32(acc[mt][nt], a[mt], b[nt][0], b[nt][1]);
        }
        __syncthreads();
    }

    #pragma unroll
    for (int mt = 0; mt < 4; mt++) {
        int r = row0 + wm * 64 + mt * 16 + g;
        #pragma unroll
        for (int nt = 0; nt < 4; nt++) {
            int n = col0 + wn * 32 + nt * 8 + cc * 2;
            float2 bb = *reinterpret_cast<const float2*>(bias + n);
            float2 o0, o1;
            o0.x = acc[mt][nt][0] + bb.x;
            o0.y = acc[mt][nt][1] + bb.y;
            o1.x = acc[mt][nt][2] + bb.x;
            o1.y = acc[mt][nt][3] + bb.y;
            *reinterpret_cast<float2*>(C + (size_t)r * N + n)       = o0;
            *reinterpret_cast<float2*>(C + (size_t)(r + 8) * N + n) = o1;
        }
    }
}

// ---------------------------------------------------------------------------
// Tensor-core causal flash attention (tf32 mma, FA2 online softmax).
// Grid: (T/64, B*H). 128 threads = 4 warps; each warp owns 16 query rows.
// Q is hi/lo-split tf32 (near-fp32 S); P and V single tf32.
// ---------------------------------------------------------------------------
#define AQ  64
#define AKV 64
#define KSTR 68   // K smem row stride (floats): b-frag bank = 4g+cc, bijective
#define VSTR 72   // V smem row stride (floats): b-frag bank = 8cc+g, bijective

__global__ __launch_bounds__(128) void attn_mma_kernel()
{
    __shared__ __align__(16) float Ks[AKV][KSTR];
    __shared__ __align__(16) float Vs[AKV][VSTR];

    const int qt   = blockIdx.x;
    const int bh   = blockIdx.y;
    const int b    = bh >> 4;
    const int h    = bh & 15;
    const int tid  = threadIdx.x;
    const int warp = tid >> 5;
    const int lane = tid & 31;
    const int g    = lane >> 2;
    const int cc   = lane & 3;

    const int q0      = qt * AQ;
    const int rowbase = q0 + warp * 16;
    const float* qkv_b = g_qkv + (size_t)b * Td * 3 * Cd;

    // ---- Q a-fragments, hi/lo tf32 split, pre-scaled by 1/sqrt(D) ----
    uint32_t qh[8][4], ql[8][4];
    {
        const float scale = 0.125f;
        const float* r0p = qkv_b + (size_t)(rowbase + g) * 3 * Cd + h * Dd;
        const float* r1p = qkv_b + (size_t)(rowbase + g + 8) * 3 * Cd + h * Dd;
        #pragma unroll
        for (int ks = 0; ks < 8; ks++) {
            float v[4];
            v[0] = r0p[ks * 8 + cc]     * scale;
            v[1] = r1p[ks * 8 + cc]     * scale;
            v[2] = r0p[ks * 8 + cc + 4] * scale;
            v[3] = r1p[ks * 8 + cc + 4] * scale;
            #pragma unroll
            for (int r = 0; r < 4; r++) {
                uint32_t hi = f2tf32(v[r]);
                qh[ks][r] = hi;
                ql[ks][r] = f2tf32(v[r] - __uint_as_float(hi));
            }
        }
    }

    float oc[8][4];
    #pragma unroll
    for (int nt = 0; nt < 8; nt++)
        #pragma unroll
        for (int r = 0; r < 4; r++) oc[nt][r] = 0.0f;

    float m0 = -INFINITY, m1 = -INFINITY, l0 = 0.0f, l1 = 0.0f;

    const int ntiles = qt + 1;
    const unsigned FULL = 0xffffffffu;
    const int src_a = (lane & ~3) | (cc >> 1);
    const int src_c = src_a + 2;

    for (int kt = 0; kt < ntiles; kt++) {
        const int kv0 = kt * AKV;
        __syncthreads();
        // Stage K and V tiles (tf32-rounded at store)
        #pragma unroll
        for (int i = 0; i < 8; i++) {
            int idx = tid + i * 128;
            int r   = idx >> 4;
            int c4  = (idx & 15) * 4;
            const float* src = qkv_b + (size_t)(kv0 + r) * 3 * Cd + h * Dd;
            float4 kv = *reinterpret_cast<const float4*>(src + Cd + c4);
            float4 vv = *reinterpret_cast<const float4*>(src + 2 * Cd + c4);
            float4 kw, vw;
            kw.x = __uint_as_float(f2tf32(kv.x));
            kw.y = __uint_as_float(f2tf32(kv.y));
            kw.z = __uint_as_float(f2tf32(kv.z));
            kw.w = __uint_as_float(f2tf32(kv.w));
            vw.x = __uint_as_float(f2tf32(vv.x));
            vw.y = __uint_as_float(f2tf32(vv.y));
            vw.z = __uint_as_float(f2tf32(vv.z));
            vw.w = __uint_as_float(f2tf32(vv.w));
            *reinterpret_cast<float4*>(&Ks[r][c4]) = kw;
            *reinterpret_cast<float4*>(&Vs[r][c4]) = vw;
        }
        __syncthreads();

        // ---- S = Q @ K^T (hi + lo) ----
        float sc[8][4];
        #pragma unroll
        for (int nt = 0; nt < 8; nt++)
            #pragma unroll
            for (int r = 0; r < 4; r++) sc[nt][r] = 0.0f;

        #pragma unroll
        for (int ks = 0; ks < 8; ks++) {
            #pragma unroll
            for (int nt = 0; nt < 8; nt++) {
                uint32_t kb0 = __float_as_uint(Ks[nt * 8 + g][ks * 8 + cc]);
                uint32_t kb1 = __float_as_uint(Ks[nt * 8 + g][ks * 8 + cc + 4]);
                mma_tf32(sc[nt], qh[ks], kb0, kb1);
                mma_tf32(sc[nt], ql[ks], kb0, kb1);
            }
        }

        // ---- causal mask (diagonal tile only) ----
        if (kv0 == q0) {
            const int r0 = rowbase + g;
            const int r1 = r0 + 8;
            #pragma unroll
            for (int nt = 0; nt < 8; nt++) {
                int key = kv0 + nt * 8 + 2 * cc;
                if (key     > r0) sc[nt][0] = -1e30f;
                if (key + 1 > r0) sc[nt][1] = -1e30f;
                if (key     > r1) sc[nt][2] = -1e30f;
                if (key + 1 > r1) sc[nt][3] = -1e30f;
            }
        }

        // ---- online softmax ----
        float rm0 = -1e30f, rm1 = -1e30f;
        #pragma unroll
        for (int nt = 0; nt < 8; nt++) {
            rm0 = fmaxf(rm0, fmaxf(sc[nt][0], sc[nt][1]));
            rm1 = fmaxf(rm1, fmaxf(sc[nt][2], sc[nt][3]));
        }
        rm0 = fmaxf(rm0, __shfl_xor_sync(FULL, rm0, 1));
        rm0 = fmaxf(rm0, __shfl_xor_sync(FULL, rm0, 2));
        rm1 = fmaxf(rm1, __shfl_xor_sync(FULL, rm1, 1));
        rm1 = fmaxf(rm1, __shfl_xor_sync(FULL, rm1, 2));

        const float mn0 = fmaxf(m0, rm0);
        const float mn1 = fmaxf(m1, rm1);
        const float e0  = __expf(m0 - mn0);
        const float e1  = __expf(m1 - mn1);
        m0 = mn0; m1 = mn1;

        float rs0 = 0.0f, rs1 = 0.0f;
        #pragma unroll
        for (int nt = 0; nt < 8; nt++) {
            sc[nt][0] = __expf(sc[nt][0] - mn0);
            sc[nt][1] = __expf(sc[nt][1] - mn0);
            sc[nt][2] = __expf(sc[nt][2] - mn1);
            sc[nt][3] = __expf(sc[nt][3] - mn1);
            rs0 += sc[nt][0] + sc[nt][1];
            rs1 += sc[nt][2] + sc[nt][3];
        }
        rs0 += __shfl_xor_sync(FULL, rs0, 1);
        rs0 += __shfl_xor_sync(FULL, rs0, 2);
        rs1 += __shfl_xor_sync(FULL, rs1, 1);
        rs1 += __shfl_xor_sync(FULL, rs1, 2);

        l0 = l0 * e0 + rs0;
        l1 = l1 * e1 + rs1;

        #pragma unroll
        for (int nt = 0; nt < 8; nt++) {
            oc[nt][0] *= e0; oc[nt][1] *= e0;
            oc[nt][2] *= e1; oc[nt][3] *= e1;
        }

        // ---- O += P @ V : redistribute c-frag -> a-frag via shuffles ----
        #pragma unroll
        for (int ks = 0; ks < 8; ks++) {
            float y0 = __shfl_sync(FULL, sc[ks][0], src_a);
            float y1 = __shfl_sync(FULL, sc[ks][1], src_a);
            float z0 = __shfl_sync(FULL, sc[ks][0], src_c);
            float z1 = __shfl_sync(FULL, sc[ks][1], src_c);
            float w0 = __shfl_sync(FULL, sc[ks][2], src_a);
            float w1 = __shfl_sync(FULL, sc[ks][3], src_a);
            float x0 = __shfl_sync(FULL, sc[ks][2], src_c);
            float x1 = __shfl_sync(FULL, sc[ks][3], src_c);
            const bool odd = cc & 1;
            uint32_t pa[4];
            pa[0] = f2tf32(odd ? y1 : y0);   // row g,   k = 8ks+cc
            pa[1] = f2tf32(odd ? w1 : w0);   // row g+8, k = 8ks+cc
            pa[2] = f2tf32(odd ? z1 : z0);   // row g,   k = 8ks+cc+4
            pa[3] = f2tf32(odd ? x1 : x0);   // row g+8, k = 8ks+cc+4
            #pragma unroll
            for (int nt = 0; nt < 8; nt++) {
                uint32_t vb0 = __float_as_uint(Vs[ks * 8 + cc][nt * 8 + g]);
                uint32_t vb1 = __float_as_uint(Vs[ks * 8 + cc + 4][nt * 8 + g]);
                mma_tf32(oc[nt], pa, vb0, vb1);
            }
        }
    }

    // ---- epilogue: normalize, write y_att ----
    const float inv0 = 1.0f / l0;
    const float inv1 = 1.0f / l1;
    const int r0 = rowbase + g;
    float* dst0 = g_att + ((size_t)b * Td + r0) * Cd + h * Dd;
    float* dst1 = g_att + ((size_t)b * Td + r0 + 8) * Cd + h * Dd;
    #pragma unroll
    for (int nt = 0; nt < 8; nt++) {
        float2 o0, o1;
        o0.x = oc[nt][0] * inv0;
        o0.y = oc[nt][1] * inv0;
        o1.x = oc[nt][2] * inv1;
        o1.y = oc[nt][3] * inv1;
        *reinterpret_cast<float2*>(dst0 + nt * 8 + 2 * cc) = o0;
        *reinterpret_cast<float2*>(dst1 + nt * 8 + 2 * cc) = o1;
    }
}

// ---------------------------------------------------------------------------
// Launch
// ---------------------------------------------------------------------------
extern "C" void kernel_launch(void* const* d_in, const int* in_sizes, int n_in,
                              void* d_out, int out_size)
{
    const float* x      = (const float*)d_in[0];
    // d_in[1] = attn_mask: tril by construction; causality handled structurally
    const float* W_attn = (const float*)d_in[2];
    const float* b_attn = (const float*)d_in[3];
    const float* W_proj = (const float*)d_in[4];
    const float* b_proj = (const float*)d_in[5];
    float* out = (float*)d_out;

    float* qkv = nullptr;
    float* att = nullptr;
    cudaGetSymbolAddress((void**)&qkv, g_qkv);
    cudaGetSymbolAddress((void**)&att, g_att);

    const int M = Bd * Td;     // 4096

    // 1) QKV = x @ W_attn + b_attn : [4096,1024] x [1024,3072]
    {
        dim3 grid((3 * Cd) / GBN, M / GBM);
        gemm_tf32_bias<<<grid, 256>>>(x, W_attn, b_attn, qkv, M, 3 * Cd, Cd);
    }
    // 2) causal attention per (b,h), tensor-core
    {
        dim3 grid(Td / AQ, Bd * Hd);
        attn_mma_kernel<<<grid, 128>>>();
    }
    // 3) out = att @ W_proj + b_proj : [4096,1024] x [1024,1024]
    {
        dim3 grid(Cd / GBN, M / GBM);
        gemm_tf32_bias<<<grid, 256>>>(att, W_proj, b_proj, out, M, Cd, Cd);
    }
}

// round 5
// speedup vs baseline: 2.1998x; 1.0349x over previous
#include <cuda_runtime.h>
#include <math.h>
#include <stdint.h>

// Problem dims (fixed by the dataset)
#define Bd 2
#define Td 2048
#define Cd 1024
#define Hd 16
#define Dd 64

// Scratch: qkv [B,T,3C] and attention output [B,T,C]
__device__ float g_qkv[(size_t)Bd * Td * 3 * Cd];
__device__ float g_att[(size_t)Bd * Td * Cd];

__device__ __forceinline__ uint32_t f2tf32(float x) {
    uint32_t r;
    asm("cvt.rna.tf32.f32 %0, %1;" : "=r"(r) : "f"(x));
    return r;
}

__device__ __forceinline__ void mma_tf32(float* c, const uint32_t* a,
                                         uint32_t b0, uint32_t b1) {
    asm volatile(
        "mma.sync.aligned.m16n8k8.row.col.f32.tf32.tf32.f32 "
        "{%0,%1,%2,%3}, {%4,%5,%6,%7}, {%8,%9}, {%0,%1,%2,%3};"
        : "+f"(c[0]), "+f"(c[1]), "+f"(c[2]), "+f"(c[3])
        : "r"(a[0]), "r"(a[1]), "r"(a[2]), "r"(a[3]), "r"(b0), "r"(b1));
}

__device__ __forceinline__ void cp_async16(void* smem, const void* gmem) {
    uint32_t s = (uint32_t)__cvta_generic_to_shared(smem);
    asm volatile("cp.async.cg.shared.global [%0], [%1], 16;" :: "r"(s), "l"(gmem));
}
__device__ __forceinline__ void cp_commit() {
    asm volatile("cp.async.commit_group;");
}
__device__ __forceinline__ void cp_wait0() {
    asm volatile("cp.async.wait_group 0;");
}

// ---------------------------------------------------------------------------
// TF32 tensor-core GEMM + bias, cp.async double-buffered.
// 128x128 block tile, BK=32, 8 warps (2x4), 64x32 warp tile, m16n8k8 mma.
// Raw fp32 staged in SMEM; cvt.rna.tf32 at fragment load (same accuracy).
// ---------------------------------------------------------------------------
#define GBM 128
#define GBN 128
#define GBK 32

#define ASTR (GBK + 4)     // As row stride (floats); 144B, 16B-aligned
#define BSTR (GBN + 8)     // Bs row stride (floats); 544B, 16B-aligned
#define ASZ  (GBM * ASTR)  // one stage of As
#define BSZ  (GBK * BSTR)  // one stage of Bs

__global__ __launch_bounds__(256) void gemm_tf32_bias(
    const float* __restrict__ A, const float* __restrict__ B,
    const float* __restrict__ bias, float* __restrict__ C,
    int M, int N, int K)
{
    extern __shared__ __align__(16) float smem[];
    float* As = smem;                 // [2][GBM][ASTR]
    float* Bs = smem + 2 * ASZ;       // [2][GBK][BSTR]

    const int tid  = threadIdx.x;
    const int warp = tid >> 5;
    const int lane = tid & 31;
    const int wm = warp >> 2;
    const int wn = warp & 3;
    const int g  = lane >> 2;
    const int cc = lane & 3;

    const int row0 = blockIdx.y * GBM;
    const int col0 = blockIdx.x * GBN;

    const float* Abase = A + (size_t)row0 * K;
    const float* Bbase = B + col0;

    // per-thread staging coordinates
    const int ar  = tid >> 3;          // 0..127 (A row, via idx=tid+i*256 -> +32/iter)
    const int ac4 = (tid & 7) * 4;     // A col group
    const int br  = tid >> 5;          // 0..31 step 8
    const int bc4 = (tid & 31) * 4;

    float acc[4][4][4];
    #pragma unroll
    for (int mt = 0; mt < 4; mt++)
        #pragma unroll
        for (int nt = 0; nt < 4; nt++)
            #pragma unroll
            for (int q = 0; q < 4; q++) acc[mt][nt][q] = 0.0f;

    // prologue: stage 0
    #pragma unroll
    for (int i = 0; i < 4; i++)
        cp_async16(&As[(ar + i * 32) * ASTR + ac4],
                   Abase + (size_t)(ar + i * 32) * K + ac4);
    #pragma unroll
    for (int i = 0; i < 4; i++)
        cp_async16(&Bs[(br + i * 8) * BSTR + bc4],
                   Bbase + (size_t)(br + i * 8) * N + bc4);
    cp_commit();

    int buf = 0;
    for (int k0 = 0; k0 < K; k0 += GBK) {
        cp_wait0();
        __syncthreads();   // stage `buf` visible to all; prior reads of buf^1 done

        if (k0 + GBK < K) {
            const int nb = buf ^ 1;
            #pragma unroll
            for (int i = 0; i < 4; i++)
                cp_async16(&As[nb * ASZ + (ar + i * 32) * ASTR + ac4],
                           Abase + (size_t)(ar + i * 32) * K + k0 + GBK + ac4);
            #pragma unroll
            for (int i = 0; i < 4; i++)
                cp_async16(&Bs[nb * BSZ + (br + i * 8) * BSTR + bc4],
                           Bbase + (size_t)(k0 + GBK + br + i * 8) * N + bc4);
            cp_commit();
        }

        const float* Ab = As + buf * ASZ;
        const float* Bb = Bs + buf * BSZ;
        #pragma unroll
        for (int kk = 0; kk < GBK / 8; kk++) {
            const int kc = kk * 8 + cc;
            uint32_t a[4][4];
            #pragma unroll
            for (int mt = 0; mt < 4; mt++) {
                int r = wm * 64 + mt * 16 + g;
                a[mt][0] = f2tf32(Ab[r * ASTR + kc]);
                a[mt][1] = f2tf32(Ab[(r + 8) * ASTR + kc]);
                a[mt][2] = f2tf32(Ab[r * ASTR + kc + 4]);
                a[mt][3] = f2tf32(Ab[(r + 8) * ASTR + kc + 4]);
            }
            uint32_t b[4][2];
            #pragma unroll
            for (int nt = 0; nt < 4; nt++) {
                int n = wn * 32 + nt * 8 + g;
                b[nt][0] = f2tf32(Bb[kc * BSTR + n]);
                b[nt][1] = f2tf32(Bb[(kc + 4) * BSTR + n]);
            }
            #pragma unroll
            for (int mt = 0; mt < 4; mt++)
                #pragma unroll
                for (int nt = 0; nt < 4; nt++)
                    mma_tf32(acc[mt][nt], a[mt], b[nt][0], b[nt][1]);
        }
        buf ^= 1;
    }

    #pragma unroll
    for (int mt = 0; mt < 4; mt++) {
        int r = row0 + wm * 64 + mt * 16 + g;
        #pragma unroll
        for (int nt = 0; nt < 4; nt++) {
            int n = col0 + wn * 32 + nt * 8 + cc * 2;
            float2 bb = *reinterpret_cast<const float2*>(bias + n);
            float2 o0, o1;
            o0.x = acc[mt][nt][0] + bb.x;
            o0.y = acc[mt][nt][1] + bb.y;
            o1.x = acc[mt][nt][2] + bb.x;
            o1.y = acc[mt][nt][3] + bb.y;
            *reinterpret_cast<float2*>(C + (size_t)r * N + n)       = o0;
            *reinterpret_cast<float2*>(C + (size_t)(r + 8) * N + n) = o1;
        }
    }
}

// ---------------------------------------------------------------------------
// Tensor-core causal flash attention (tf32 mma, FA2 online softmax).
// Grid: (T/128, B*H). 256 threads = 8 warps; each warp owns 16 query rows.
// Q is hi/lo-split tf32 (near-fp32 S); P and V single tf32.
// ---------------------------------------------------------------------------
#define AQ  128
#define AKV 64
#define KSTR 68   // K smem row stride (floats): b-frag bank = 4g+cc, bijective
#define VSTR 72   // V smem row stride (floats): b-frag bank = 8cc+g, bijective

__global__ __launch_bounds__(256) void attn_mma_kernel()
{
    __shared__ __align__(16) float Ks[AKV][KSTR];
    __shared__ __align__(16) float Vs[AKV][VSTR];

    const int qt   = blockIdx.x;
    const int bh   = blockIdx.y;
    const int b    = bh >> 4;
    const int h    = bh & 15;
    const int tid  = threadIdx.x;
    const int warp = tid >> 5;
    const int lane = tid & 31;
    const int g    = lane >> 2;
    const int cc   = lane & 3;

    const int q0      = qt * AQ;
    const int rowbase = q0 + warp * 16;
    const float* qkv_b = g_qkv + (size_t)b * Td * 3 * Cd;

    // ---- Q a-fragments, hi/lo tf32 split, pre-scaled by 1/sqrt(D) ----
    uint32_t qh[8][4], ql[8][4];
    {
        const float scale = 0.125f;
        const float* r0p = qkv_b + (size_t)(rowbase + g) * 3 * Cd + h * Dd;
        const float* r1p = qkv_b + (size_t)(rowbase + g + 8) * 3 * Cd + h * Dd;
        #pragma unroll
        for (int ks = 0; ks < 8; ks++) {
            float v[4];
            v[0] = r0p[ks * 8 + cc]     * scale;
            v[1] = r1p[ks * 8 + cc]     * scale;
            v[2] = r0p[ks * 8 + cc + 4] * scale;
            v[3] = r1p[ks * 8 + cc + 4] * scale;
            #pragma unroll
            for (int r = 0; r < 4; r++) {
                uint32_t hi = f2tf32(v[r]);
                qh[ks][r] = hi;
                ql[ks][r] = f2tf32(v[r] - __uint_as_float(hi));
            }
        }
    }

    float oc[8][4];
    #pragma unroll
    for (int nt = 0; nt < 8; nt++)
        #pragma unroll
        for (int r = 0; r < 4; r++) oc[nt][r] = 0.0f;

    float m0 = -INFINITY, m1 = -INFINITY, l0 = 0.0f, l1 = 0.0f;

    const int ntiles = (q0 + AQ) / AKV;
    const unsigned FULL = 0xffffffffu;
    const int src_a = (lane & ~3) | (cc >> 1);
    const int src_c = src_a + 2;

    for (int kt = 0; kt < ntiles; kt++) {
        const int kv0 = kt * AKV;
        __syncthreads();
        // Stage K and V tiles (tf32-rounded at store): 1024 float4 each, 256 thr
        #pragma unroll
        for (int i = 0; i < 4; i++) {
            int idx = tid + i * 256;
            int r   = idx >> 4;
            int c4  = (idx & 15) * 4;
            const float* src = qkv_b + (size_t)(kv0 + r) * 3 * Cd + h * Dd;
            float4 kv = *reinterpret_cast<const float4*>(src + Cd + c4);
            float4 vv = *reinterpret_cast<const float4*>(src + 2 * Cd + c4);
            float4 kw, vw;
            kw.x = __uint_as_float(f2tf32(kv.x));
            kw.y = __uint_as_float(f2tf32(kv.y));
            kw.z = __uint_as_float(f2tf32(kv.z));
            kw.w = __uint_as_float(f2tf32(kv.w));
            vw.x = __uint_as_float(f2tf32(vv.x));
            vw.y = __uint_as_float(f2tf32(vv.y));
            vw.z = __uint_as_float(f2tf32(vv.z));
            vw.w = __uint_as_float(f2tf32(vv.w));
            *reinterpret_cast<float4*>(&Ks[r][c4]) = kw;
            *reinterpret_cast<float4*>(&Vs[r][c4]) = vw;
        }
        __syncthreads();

        // Fully masked for this warp? (all keys beyond all of its rows)
        if (kv0 > rowbase + 15) continue;

        // ---- S = Q @ K^T (hi + lo) ----
        float sc[8][4];
        #pragma unroll
        for (int nt = 0; nt < 8; nt++)
            #pragma unroll
            for (int r = 0; r < 4; r++) sc[nt][r] = 0.0f;

        #pragma unroll
        for (int ks = 0; ks < 8; ks++) {
            #pragma unroll
            for (int nt = 0; nt < 8; nt++) {
                uint32_t kb0 = __float_as_uint(Ks[nt * 8 + g][ks * 8 + cc]);
                uint32_t kb1 = __float_as_uint(Ks[nt * 8 + g][ks * 8 + cc + 4]);
                mma_tf32(sc[nt], qh[ks], kb0, kb1);
                mma_tf32(sc[nt], ql[ks], kb0, kb1);
            }
        }

        // ---- causal mask (tiles overlapping this warp's rows) ----
        if (kv0 + AKV - 1 > rowbase) {
            const int r0 = rowbase + g;
            const int r1 = r0 + 8;
            #pragma unroll
            for (int nt = 0; nt < 8; nt++) {
                int key = kv0 + nt * 8 + 2 * cc;
                if (key     > r0) sc[nt][0] = -1e30f;
                if (key + 1 > r0) sc[nt][1] = -1e30f;
                if (key     > r1) sc[nt][2] = -1e30f;
                if (key + 1 > r1) sc[nt][3] = -1e30f;
            }
        }

        // ---- online softmax ----
        float rm0 = -1e30f, rm1 = -1e30f;
        #pragma unroll
        for (int nt = 0; nt < 8; nt++) {
            rm0 = fmaxf(rm0, fmaxf(sc[nt][0], sc[nt][1]));
            rm1 = fmaxf(rm1, fmaxf(sc[nt][2], sc[nt][3]));
        }
        rm0 = fmaxf(rm0, __shfl_xor_sync(FULL, rm0, 1));
        rm0 = fmaxf(rm0, __shfl_xor_sync(FULL, rm0, 2));
        rm1 = fmaxf(rm1, __shfl_xor_sync(FULL, rm1, 1));
        rm1 = fmaxf(rm1, __shfl_xor_sync(FULL, rm1, 2));

        const float mn0 = fmaxf(m0, rm0);
        const float mn1 = fmaxf(m1, rm1);
        const float e0  = __expf(m0 - mn0);
        const float e1  = __expf(m1 - mn1);
        m0 = mn0; m1 = mn1;

        float rs0 = 0.0f, rs1 = 0.0f;
        #pragma unroll
        for (int nt = 0; nt < 8; nt++) {
            sc[nt][0] = __expf(sc[nt][0] - mn0);
            sc[nt][1] = __expf(sc[nt][1] - mn0);
            sc[nt][2] = __expf(sc[nt][2] - mn1);
            sc[nt][3] = __expf(sc[nt][3] - mn1);
            rs0 += sc[nt][0] + sc[nt][1];
            rs1 += sc[nt][2] + sc[nt][3];
        }
        rs0 += __shfl_xor_sync(FULL, rs0, 1);
        rs0 += __shfl_xor_sync(FULL, rs0, 2);
        rs1 += __shfl_xor_sync(FULL, rs1, 1);
        rs1 += __shfl_xor_sync(FULL, rs1, 2);

        l0 = l0 * e0 + rs0;
        l1 = l1 * e1 + rs1;

        #pragma unroll
        for (int nt = 0; nt < 8; nt++) {
            oc[nt][0] *= e0; oc[nt][1] *= e0;
            oc[nt][2] *= e1; oc[nt][3] *= e1;
        }

        // ---- O += P @ V : redistribute c-frag -> a-frag via shuffles ----
        #pragma unroll
        for (int ks = 0; ks < 8; ks++) {
            float y0 = __shfl_sync(FULL, sc[ks][0], src_a);
            float y1 = __shfl_sync(FULL, sc[ks][1], src_a);
            float z0 = __shfl_sync(FULL, sc[ks][0], src_c);
            float z1 = __shfl_sync(FULL, sc[ks][1], src_c);
            float w0 = __shfl_sync(FULL, sc[ks][2], src_a);
            float w1 = __shfl_sync(FULL, sc[ks][3], src_a);
            float x0 = __shfl_sync(FULL, sc[ks][2], src_c);
            float x1 = __shfl_sync(FULL, sc[ks][3], src_c);
            const bool odd = cc & 1;
            uint32_t pa[4];
            pa[0] = f2tf32(odd ? y1 : y0);   // row g,   k = 8ks+cc
            pa[1] = f2tf32(odd ? w1 : w0);   // row g+8, k = 8ks+cc
            pa[2] = f2tf32(odd ? z1 : z0);   // row g,   k = 8ks+cc+4
            pa[3] = f2tf32(odd ? x1 : x0);   // row g+8, k = 8ks+cc+4
            #pragma unroll
            for (int nt = 0; nt < 8; nt++) {
                uint32_t vb0 = __float_as_uint(Vs[ks * 8 + cc][nt * 8 + g]);
                uint32_t vb1 = __float_as_uint(Vs[ks * 8 + cc + 4][nt * 8 + g]);
                mma_tf32(oc[nt], pa, vb0, vb1);
            }
        }
    }

    // ---- epilogue: normalize, write y_att ----
    const float inv0 = 1.0f / l0;
    const float inv1 = 1.0f / l1;
    const int r0 = rowbase + g;
    float* dst0 = g_att + ((size_t)b * Td + r0) * Cd + h * Dd;
    float* dst1 = g_att + ((size_t)b * Td + r0 + 8) * Cd + h * Dd;
    #pragma unroll
    for (int nt = 0; nt < 8; nt++) {
        float2 o0, o1;
        o0.x = oc[nt][0] * inv0;
        o0.y = oc[nt][1] * inv0;
        o1.x = oc[nt][2] * inv1;
        o1.y = oc[nt][3] * inv1;
        *reinterpret_cast<float2*>(dst0 + nt * 8 + 2 * cc) = o0;
        *reinterpret_cast<float2*>(dst1 + nt * 8 + 2 * cc) = o1;
    }
}

// ---------------------------------------------------------------------------
// Launch
// ---------------------------------------------------------------------------
extern "C" void kernel_launch(void* const* d_in, const int* in_sizes, int n_in,
                              void* d_out, int out_size)
{
    const float* x      = (const float*)d_in[0];
    // d_in[1] = attn_mask: tril by construction; causality handled structurally
    const float* W_attn = (const float*)d_in[2];
    const float* b_attn = (const float*)d_in[3];
    const float* W_proj = (const float*)d_in[4];
    const float* b_proj = (const float*)d_in[5];
    float* out = (float*)d_out;

    float* qkv = nullptr;
    float* att = nullptr;
    cudaGetSymbolAddress((void**)&qkv, g_qkv);
    cudaGetSymbolAddress((void**)&att, g_att);

    const int M = Bd * Td;     // 4096
    const int GEMM_SMEM = (2 * ASZ + 2 * BSZ) * (int)sizeof(float);  // ~70 KB

    static bool attr_set = false;
    if (!attr_set) {
        cudaFuncSetAttribute(gemm_tf32_bias,
                             cudaFuncAttributeMaxDynamicSharedMemorySize,
                             GEMM_SMEM);
        attr_set = true;
    }

    // 1) QKV = x @ W_attn + b_attn : [4096,1024] x [1024,3072]
    {
        dim3 grid((3 * Cd) / GBN, M / GBM);
        gemm_tf32_bias<<<grid, 256, GEMM_SMEM>>>(x, W_attn, b_attn, qkv, M, 3 * Cd, Cd);
    }
    // 2) causal attention per (b,h), tensor-core
    {
        dim3 grid(Td / AQ, Bd * Hd);
        attn_mma_kernel<<<grid, 256>>>();
    }
    // 3) out = att @ W_proj + b_proj : [4096,1024] x [1024,1024]
    {
        dim3 grid(Cd / GBN, M / GBM);
        gemm_tf32_bias<<<grid, 256, GEMM_SMEM>>>(att, W_proj, b_proj, out, M, Cd, Cd);
    }
}

// round 6
// speedup vs baseline: 2.3003x; 1.0457x over previous
#include <cuda_runtime.h>
#include <math.h>
#include <stdint.h>

// Problem dims (fixed by the dataset)
#define Bd 2
#define Td 2048
#define Cd 1024
#define Hd 16
#define Dd 64

// Scratch: qkv [B,T,3C] and attention output [B,T,C]
__device__ float g_qkv[(size_t)Bd * Td * 3 * Cd];
__device__ float g_att[(size_t)Bd * Td * Cd];

__device__ __forceinline__ uint32_t f2tf32(float x) {
    uint32_t r;
    asm("cvt.rna.tf32.f32 %0, %1;" : "=r"(r) : "f"(x));
    return r;
}

__device__ __forceinline__ void mma_tf32(float* c, const uint32_t* a,
                                         uint32_t b0, uint32_t b1) {
    asm volatile(
        "mma.sync.aligned.m16n8k8.row.col.f32.tf32.tf32.f32 "
        "{%0,%1,%2,%3}, {%4,%5,%6,%7}, {%8,%9}, {%0,%1,%2,%3};"
        : "+f"(c[0]), "+f"(c[1]), "+f"(c[2]), "+f"(c[3])
        : "r"(a[0]), "r"(a[1]), "r"(a[2]), "r"(a[3]), "r"(b0), "r"(b1));
}

// ldmatrix x4: four 8x8 b16 tiles (== four 8x4 b32 tiles)
__device__ __forceinline__ void ldmx4(uint32_t* r, const void* p) {
    uint32_t s = (uint32_t)__cvta_generic_to_shared(p);
    asm volatile("ldmatrix.sync.aligned.m8n8.x4.shared.b16 {%0,%1,%2,%3}, [%4];"
        : "=r"(r[0]), "=r"(r[1]), "=r"(r[2]), "=r"(r[3]) : "r"(s));
}

__device__ __forceinline__ void cp_async16(void* smem, const void* gmem) {
    uint32_t s = (uint32_t)__cvta_generic_to_shared(smem);
    asm volatile("cp.async.cg.shared.global [%0], [%1], 16;" :: "r"(s), "l"(gmem));
}
__device__ __forceinline__ void cp_commit() {
    asm volatile("cp.async.commit_group;");
}
__device__ __forceinline__ void cp_wait0() {
    asm volatile("cp.async.wait_group 0;");
}

// ---------------------------------------------------------------------------
// TF32 tensor-core GEMM + bias, cp.async double-buffered.
// 128x128 block tile, BK=32, 8 warps (2x4), 64x32 warp tile, m16n8k8 mma.
// Raw fp32 staged via cp.async; converted to tf32 IN SMEM by a prepass
// (each thread converts what it staged), so the inner loop is pure
// ldmatrix/LDS + MMA with no cvt.
// ---------------------------------------------------------------------------
#define GBM 128
#define GBN 128
#define GBK 32

#define ASTR (GBK + 4)     // 144B rows: 16B-aligned, ldmatrix conflict-free
#define BSTR (GBN + 8)
#define ASZ  (GBM * ASTR)
#define BSZ  (GBK * BSTR)

__global__ __launch_bounds__(256) void gemm_tf32_bias(
    const float* __restrict__ A, const float* __restrict__ B,
    const float* __restrict__ bias, float* __restrict__ C,
    int M, int N, int K)
{
    extern __shared__ __align__(16) float smem[];
    float* As = smem;                 // [2][GBM][ASTR]
    float* Bs = smem + 2 * ASZ;       // [2][GBK][BSTR]

    const int tid  = threadIdx.x;
    const int warp = tid >> 5;
    const int lane = tid & 31;
    const int wm = warp >> 2;
    const int wn = warp & 3;
    const int g  = lane >> 2;
    const int cc = lane & 3;

    const int row0 = blockIdx.y * GBM;
    const int col0 = blockIdx.x * GBN;

    const float* Abase = A + (size_t)row0 * K;
    const float* Bbase = B + col0;

    // per-thread staging coordinates
    const int ar  = tid >> 3;
    const int ac4 = (tid & 7) * 4;
    const int br  = tid >> 5;
    const int bc4 = (tid & 31) * 4;

    // ldmatrix lane addressing for A fragments
    const int lm_row = lane & 7;
    const int lm_r8  = (lane >> 3) & 1;   // +8 rows for quads 1,3
    const int lm_c4  = (lane >> 4) * 4;   // +4 cols for quads 2,3

    float acc[4][4][4];
    #pragma unroll
    for (int mt = 0; mt < 4; mt++)
        #pragma unroll
        for (int nt = 0; nt < 4; nt++)
            #pragma unroll
            for (int q = 0; q < 4; q++) acc[mt][nt][q] = 0.0f;

    // prologue: stage 0
    #pragma unroll
    for (int i = 0; i < 4; i++)
        cp_async16(&As[(ar + i * 32) * ASTR + ac4],
                   Abase + (size_t)(ar + i * 32) * K + ac4);
    #pragma unroll
    for (int i = 0; i < 4; i++)
        cp_async16(&Bs[(br + i * 8) * BSTR + bc4],
                   Bbase + (size_t)(br + i * 8) * N + bc4);
    cp_commit();

    int buf = 0;
    for (int k0 = 0; k0 < K; k0 += GBK) {
        cp_wait0();
        __syncthreads();   // raw stage `buf` visible; prior reads of buf^1 done

        // ---- prepass: convert this thread's staged elements in place ----
        float* Ab = As + buf * ASZ;
        float* Bb = Bs + buf * BSZ;
        #pragma unroll
        for (int i = 0; i < 4; i++) {
            float4* p = reinterpret_cast<float4*>(&Ab[(ar + i * 32) * ASTR + ac4]);
            float4 v = *p;
            v.x = __uint_as_float(f2tf32(v.x));
            v.y = __uint_as_float(f2tf32(v.y));
            v.z = __uint_as_float(f2tf32(v.z));
            v.w = __uint_as_float(f2tf32(v.w));
            *p = v;
        }
        #pragma unroll
        for (int i = 0; i < 4; i++) {
            float4* p = reinterpret_cast<float4*>(&Bb[(br + i * 8) * BSTR + bc4]);
            float4 v = *p;
            v.x = __uint_as_float(f2tf32(v.x));
            v.y = __uint_as_float(f2tf32(v.y));
            v.z = __uint_as_float(f2tf32(v.z));
            v.w = __uint_as_float(f2tf32(v.w));
            *p = v;
        }

        // issue next stage while this one computes
        if (k0 + GBK < K) {
            const int nb = buf ^ 1;
            #pragma unroll
            for (int i = 0; i < 4; i++)
                cp_async16(&As[nb * ASZ + (ar + i * 32) * ASTR + ac4],
                           Abase + (size_t)(ar + i * 32) * K + k0 + GBK + ac4);
            #pragma unroll
            for (int i = 0; i < 4; i++)
                cp_async16(&Bs[nb * BSZ + (br + i * 8) * BSTR + bc4],
                           Bbase + (size_t)(k0 + GBK + br + i * 8) * N + bc4);
            cp_commit();
        }
        __syncthreads();   // converted tiles visible to all

        #pragma unroll
        for (int kk = 0; kk < GBK / 8; kk++) {
            const int kc = kk * 8 + cc;
            uint32_t a[4][4];
            #pragma unroll
            for (int mt = 0; mt < 4; mt++) {
                int r = wm * 64 + mt * 16 + lm_row + lm_r8 * 8;
                ldmx4(a[mt], &Ab[r * ASTR + kk * 8 + lm_c4]);
            }
            uint32_t b[4][2];
            #pragma unroll
            for (int nt = 0; nt < 4; nt++) {
                int n = wn * 32 + nt * 8 + g;
                b[nt][0] = __float_as_uint(Bb[kc * BSTR + n]);
                b[nt][1] = __float_as_uint(Bb[(kc + 4) * BSTR + n]);
            }
            #pragma unroll
            for (int mt = 0; mt < 4; mt++)
                #pragma unroll
                for (int nt = 0; nt < 4; nt++)
                    mma_tf32(acc[mt][nt], a[mt], b[nt][0], b[nt][1]);
        }
        buf ^= 1;
    }

    #pragma unroll
    for (int mt = 0; mt < 4; mt++) {
        int r = row0 + wm * 64 + mt * 16 + g;
        #pragma unroll
        for (int nt = 0; nt < 4; nt++) {
            int n = col0 + wn * 32 + nt * 8 + cc * 2;
            float2 bb = *reinterpret_cast<const float2*>(bias + n);
            float2 o0, o1;
            o0.x = acc[mt][nt][0] + bb.x;
            o0.y = acc[mt][nt][1] + bb.y;
            o1.x = acc[mt][nt][2] + bb.x;
            o1.y = acc[mt][nt][3] + bb.y;
            *reinterpret_cast<float2*>(C + (size_t)r * N + n)       = o0;
            *reinterpret_cast<float2*>(C + (size_t)(r + 8) * N + n) = o1;
        }
    }
}

// ---------------------------------------------------------------------------
// Tensor-core causal flash attention (tf32 mma, FA2 online softmax).
// Grid: (T/128, B*H). 256 threads = 8 warps; each warp owns 16 query rows.
// Q is hi/lo-split tf32; K fragments via ldmatrix.x4 (2 k-steps per instr).
// ---------------------------------------------------------------------------
#define AQ  128
#define AKV 64
#define KSTR 68   // 272B rows: 16B-aligned, ldmatrix conflict-free
#define VSTR 72   // V b-frag via LDS: bank = 8cc+g, bijective

__global__ __launch_bounds__(256) void attn_mma_kernel()
{
    __shared__ __align__(16) float Ks[AKV][KSTR];
    __shared__ __align__(16) float Vs[AKV][VSTR];

    const int qt   = blockIdx.x;
    const int bh   = blockIdx.y;
    const int b    = bh >> 4;
    const int h    = bh & 15;
    const int tid  = threadIdx.x;
    const int warp = tid >> 5;
    const int lane = tid & 31;
    const int g    = lane >> 2;
    const int cc   = lane & 3;

    const int q0      = qt * AQ;
    const int rowbase = q0 + warp * 16;
    const float* qkv_b = g_qkv + (size_t)b * Td * 3 * Cd;

    // ldmatrix lane addressing for K b-fragments
    const int lm_row = lane & 7;
    const int lm_c4  = (lane >> 3) * 4;   // quad -> col offset {0,4,8,12}

    // ---- Q a-fragments, hi/lo tf32 split, pre-scaled by 1/sqrt(D) ----
    uint32_t qh[8][4], ql[8][4];
    {
        const float scale = 0.125f;
        const float* r0p = qkv_b + (size_t)(rowbase + g) * 3 * Cd + h * Dd;
        const float* r1p = qkv_b + (size_t)(rowbase + g + 8) * 3 * Cd + h * Dd;
        #pragma unroll
        for (int ks = 0; ks < 8; ks++) {
            float v[4];
            v[0] = r0p[ks * 8 + cc]     * scale;
            v[1] = r1p[ks * 8 + cc]     * scale;
            v[2] = r0p[ks * 8 + cc + 4] * scale;
            v[3] = r1p[ks * 8 + cc + 4] * scale;
            #pragma unroll
            for (int r = 0; r < 4; r++) {
                uint32_t hi = f2tf32(v[r]);
                qh[ks][r] = hi;
                ql[ks][r] = f2tf32(v[r] - __uint_as_float(hi));
            }
        }
    }

    float oc[8][4];
    #pragma unroll
    for (int nt = 0; nt < 8; nt++)
        #pragma unroll
        for (int r = 0; r < 4; r++) oc[nt][r] = 0.0f;

    float m0 = -INFINITY, m1 = -INFINITY, l0 = 0.0f, l1 = 0.0f;

    const int ntiles = (q0 + AQ) / AKV;
    const unsigned FULL = 0xffffffffu;
    const int src_a = (lane & ~3) | (cc >> 1);
    const int src_c = src_a + 2;

    for (int kt = 0; kt < ntiles; kt++) {
        const int kv0 = kt * AKV;
        __syncthreads();
        // Stage K and V tiles (tf32-rounded at store): 1024 float4 each
        #pragma unroll
        for (int i = 0; i < 4; i++) {
            int idx = tid + i * 256;
            int r   = idx >> 4;
            int c4  = (idx & 15) * 4;
            const float* src = qkv_b + (size_t)(kv0 + r) * 3 * Cd + h * Dd;
            float4 kv = *reinterpret_cast<const float4*>(src + Cd + c4);
            float4 vv = *reinterpret_cast<const float4*>(src + 2 * Cd + c4);
            float4 kw, vw;
            kw.x = __uint_as_float(f2tf32(kv.x));
            kw.y = __uint_as_float(f2tf32(kv.y));
            kw.z = __uint_as_float(f2tf32(kv.z));
            kw.w = __uint_as_float(f2tf32(kv.w));
            vw.x = __uint_as_float(f2tf32(vv.x));
            vw.y = __uint_as_float(f2tf32(vv.y));
            vw.z = __uint_as_float(f2tf32(vv.z));
            vw.w = __uint_as_float(f2tf32(vv.w));
            *reinterpret_cast<float4*>(&Ks[r][c4]) = kw;
            *reinterpret_cast<float4*>(&Vs[r][c4]) = vw;
        }
        __syncthreads();

        // Fully masked for this warp?
        if (kv0 > rowbase + 15) continue;

        // ---- S = Q @ K^T (hi + lo), K frags via ldmatrix ----
        float sc[8][4];
        #pragma unroll
        for (int nt = 0; nt < 8; nt++)
            #pragma unroll
            for (int r = 0; r < 4; r++) sc[nt][r] = 0.0f;

        #pragma unroll
        for (int nt = 0; nt < 8; nt++) {
            #pragma unroll
            for (int kp = 0; kp < 4; kp++) {
                uint32_t kb[4];   // {kb0,kb1} for ks=2kp, {kb0,kb1} for ks=2kp+1
                ldmx4(kb, &Ks[nt * 8 + lm_row][kp * 16 + lm_c4]);
                mma_tf32(sc[nt], qh[2 * kp],     kb[0], kb[1]);
                mma_tf32(sc[nt], ql[2 * kp],     kb[0], kb[1]);
                mma_tf32(sc[nt], qh[2 * kp + 1], kb[2], kb[3]);
                mma_tf32(sc[nt], ql[2 * kp + 1], kb[2], kb[3]);
            }
        }

        // ---- causal mask (tiles overlapping this warp's rows) ----
        if (kv0 + AKV - 1 > rowbase) {
            const int r0 = rowbase + g;
            const int r1 = r0 + 8;
            #pragma unroll
            for (int nt = 0; nt < 8; nt++) {
                int key = kv0 + nt * 8 + 2 * cc;
                if (key     > r0) sc[nt][0] = -1e30f;
                if (key + 1 > r0) sc[nt][1] = -1e30f;
                if (key     > r1) sc[nt][2] = -1e30f;
                if (key + 1 > r1) sc[nt][3] = -1e30f;
            }
        }

        // ---- online softmax ----
        float rm0 = -1e30f, rm1 = -1e30f;
        #pragma unroll
        for (int nt = 0; nt < 8; nt++) {
            rm0 = fmaxf(rm0, fmaxf(sc[nt][0], sc[nt][1]));
            rm1 = fmaxf(rm1, fmaxf(sc[nt][2], sc[nt][3]));
        }
        rm0 = fmaxf(rm0, __shfl_xor_sync(FULL, rm0, 1));
        rm0 = fmaxf(rm0, __shfl_xor_sync(FULL, rm0, 2));
        rm1 = fmaxf(rm1, __shfl_xor_sync(FULL, rm1, 1));
        rm1 = fmaxf(rm1, __shfl_xor_sync(FULL, rm1, 2));

        const float mn0 = fmaxf(m0, rm0);
        const float mn1 = fmaxf(m1, rm1);
        const float e0  = __expf(m0 - mn0);
        const float e1  = __expf(m1 - mn1);
        m0 = mn0; m1 = mn1;

        float rs0 = 0.0f, rs1 = 0.0f;
        #pragma unroll
        for (int nt = 0; nt < 8; nt++) {
            sc[nt][0] = __expf(sc[nt][0] - mn0);
            sc[nt][1] = __expf(sc[nt][1] - mn0);
            sc[nt][2] = __expf(sc[nt][2] - mn1);
            sc[nt][3] = __expf(sc[nt][3] - mn1);
            rs0 += sc[nt][0] + sc[nt][1];
            rs1 += sc[nt][2] + sc[nt][3];
        }
        rs0 += __shfl_xor_sync(FULL, rs0, 1);
        rs0 += __shfl_xor_sync(FULL, rs0, 2);
        rs1 += __shfl_xor_sync(FULL, rs1, 1);
        rs1 += __shfl_xor_sync(FULL, rs1, 2);

        l0 = l0 * e0 + rs0;
        l1 = l1 * e1 + rs1;

        #pragma unroll
        for (int nt = 0; nt < 8; nt++) {
            oc[nt][0] *= e0; oc[nt][1] *= e0;
            oc[nt][2] *= e1; oc[nt][3] *= e1;
        }

        // ---- O += P @ V : redistribute c-frag -> a-frag via shuffles ----
        #pragma unroll
        for (int ks = 0; ks < 8; ks++) {
            float y0 = __shfl_sync(FULL, sc[ks][0], src_a);
            float y1 = __shfl_sync(FULL, sc[ks][1], src_a);
            float z0 = __shfl_sync(FULL, sc[ks][0], src_c);
            float z1 = __shfl_sync(FULL, sc[ks][1], src_c);
            float w0 = __shfl_sync(FULL, sc[ks][2], src_a);
            float w1 = __shfl_sync(FULL, sc[ks][3], src_a);
            float x0 = __shfl_sync(FULL, sc[ks][2], src_c);
            float x1 = __shfl_sync(FULL, sc[ks][3], src_c);
            const bool odd = cc & 1;
            uint32_t pa[4];
            pa[0] = f2tf32(odd ? y1 : y0);
            pa[1] = f2tf32(odd ? w1 : w0);
            pa[2] = f2tf32(odd ? z1 : z0);
            pa[3] = f2tf32(odd ? x1 : x0);
            #pragma unroll
            for (int nt = 0; nt < 8; nt++) {
                uint32_t vb0 = __float_as_uint(Vs[ks * 8 + cc][nt * 8 + g]);
                uint32_t vb1 = __float_as_uint(Vs[ks * 8 + cc + 4][nt * 8 + g]);
                mma_tf32(oc[nt], pa, vb0, vb1);
            }
        }
    }

    // ---- epilogue: normalize, write y_att ----
    const float inv0 = 1.0f / l0;
    const float inv1 = 1.0f / l1;
    const int r0 = rowbase + g;
    float* dst0 = g_att + ((size_t)b * Td + r0) * Cd + h * Dd;
    float* dst1 = g_att + ((size_t)b * Td + r0 + 8) * Cd + h * Dd;
    #pragma unroll
    for (int nt = 0; nt < 8; nt++) {
        float2 o0, o1;
        o0.x = oc[nt][0] * inv0;
        o0.y = oc[nt][1] * inv0;
        o1.x = oc[nt][2] * inv1;
        o1.y = oc[nt][3] * inv1;
        *reinterpret_cast<float2*>(dst0 + nt * 8 + 2 * cc) = o0;
        *reinterpret_cast<float2*>(dst1 + nt * 8 + 2 * cc) = o1;
    }
}

// ---------------------------------------------------------------------------
// Launch
// ---------------------------------------------------------------------------
extern "C" void kernel_launch(void* const* d_in, const int* in_sizes, int n_in,
                              void* d_out, int out_size)
{
    const float* x      = (const float*)d_in[0];
    // d_in[1] = attn_mask: tril by construction; causality handled structurally
    const float* W_attn = (const float*)d_in[2];
    const float* b_attn = (const float*)d_in[3];
    const float* W_proj = (const float*)d_in[4];
    const float* b_proj = (const float*)d_in[5];
    float* out = (float*)d_out;

    float* qkv = nullptr;
    float* att = nullptr;
    cudaGetSymbolAddress((void**)&qkv, g_qkv);
    cudaGetSymbolAddress((void**)&att, g_att);

    const int M = Bd * Td;     // 4096
    const int GEMM_SMEM = (2 * ASZ + 2 * BSZ) * (int)sizeof(float);  // ~70 KB

    static bool attr_set = false;
    if (!attr_set) {
        cudaFuncSetAttribute(gemm_tf32_bias,
                             cudaFuncAttributeMaxDynamicSharedMemorySize,
                             GEMM_SMEM);
        attr_set = true;
    }

    // 1) QKV = x @ W_attn + b_attn : [4096,1024] x [1024,3072]
    {
        dim3 grid((3 * Cd) / GBN, M / GBM);
        gemm_tf32_bias<<<grid, 256, GEMM_SMEM>>>(x, W_attn, b_attn, qkv, M, 3 * Cd, Cd);
    }
    // 2) causal attention per (b,h), tensor-core
    {
        dim3 grid(Td / AQ, Bd * Hd);
        attn_mma_kernel<<<grid, 256>>>();
    }
    // 3) out = att @ W_proj + b_proj : [4096,1024] x [1024,1024]
    {
        dim3 grid(Cd / GBN, M / GBM);
        gemm_tf32_bias<<<grid, 256, GEMM_SMEM>>>(att, W_proj, b_proj, out, M, Cd, Cd);
    }
}